// round 1
// baseline (speedup 1.0000x reference)
#include <cuda_runtime.h>

// img:  [1, 3, 4096, 4096] float32
// ys,xs: [512] int32
// out:  [256, 6, 32, 32] float32  == linearized [N=512, 3, 32, 32]
//
// out[n*3072 + c*1024 + r*32 + j] = img[c*H*W + ((ys[n]+r)%H)*W + (xs[n]+j)%W]

#define H 4096
#define W 4096
#define PH 32
#define PW 32
#define NPATCH 512
#define ELEMS_PER_PATCH (3 * PH * PW)   // 3072

__global__ __launch_bounds__(256, 8)
void patch_gather_kernel(const float* __restrict__ img,
                         const int* __restrict__ ys,
                         const int* __restrict__ xs,
                         float* __restrict__ out)
{
    const int n = blockIdx.x;
    const int y0 = ys[n];
    const int x0 = xs[n];

    float* __restrict__ out_n = out + (size_t)n * ELEMS_PER_PATCH;

    // 256 threads, 12 iterations: e = tid + k*256, e in [0, 3072)
    // e = c*1024 + r*32 + j ; consecutive tid -> consecutive j (coalesced)
    #pragma unroll
    for (int k = 0; k < ELEMS_PER_PATCH / 256; k++) {
        const int e = threadIdx.x + (k << 8);
        const int j = e & 31;
        const int r = (e >> 5) & 31;
        const int c = e >> 10;

        int yy = y0 + r; if (yy >= H) yy -= H;
        int xx = x0 + j; if (xx >= W) xx -= W;

        out_n[e] = __ldg(img + ((size_t)c * H + yy) * W + xx);
    }
}

extern "C" void kernel_launch(void* const* d_in, const int* in_sizes, int n_in,
                              void* d_out, int out_size)
{
    const float* img = (const float*)d_in[0];
    const int*   ys  = (const int*)d_in[1];
    const int*   xs  = (const int*)d_in[2];
    float* out = (float*)d_out;

    patch_gather_kernel<<<NPATCH, 256>>>(img, ys, xs, out);
}